// round 16
// baseline (speedup 1.0000x reference)
#include <cuda_runtime.h>
#include <cstdint>

// CenterLoss collapses algebraically: after masking, only the true-label
// column survives; the other C-1 zeros clamp to 1e-12 each.
//   loss = sum_n clamp(||x_n - c_{lab_n}||^2, 1e-12, 1e12) + N*(C-1)*1e-12
//
// R16 = R15 resubmit (prior round was an infra failure, no measurement).
// MSHR-bypass experiment: ten LDG-path variants all pinned at ~1.88 TB/s,
// consistent with a per-SM in-flight-bytes cap (L1tex MSHR/sector tracking)
// at parked-clock DRAM latency. cp.async.bulk (UBLKCP) is tracked by the
// bulk engine, NOT per-warp MSHRs -> the one untested memory path.
// Per CTA: 1 bulk copy of 4 contiguous x rows (8KB) + 4 bulk copies of
// gathered center rows (2KB each) into smem, mbarrier expect_tx=16KB,
// compute from smem. Tail = locked best config, fixed-order, deterministic.

#define N_ROWS 4096      // 16 * 256
#define FEAT_DIM 512
#define NUM_CLASSES 10000
#define NUM_CTAS 1024
#define ROWS_PER_CTA 4
#define TX_BYTES (ROWS_PER_CTA * FEAT_DIM * 4 * 2)   // 16384

__device__ float g_cta_partials[NUM_CTAS];
__device__ unsigned int g_done_count = 0;

__device__ __forceinline__ uint32_t smem_u32(const void* p)
{
    uint32_t a;
    asm("{ .reg .u64 t; cvta.to.shared.u64 t, %1; cvt.u32.u64 %0, t; }"
        : "=r"(a) : "l"(p));
    return a;
}

__global__ __launch_bounds__(256, 8) void center_loss_kernel(
    const float* __restrict__ x,
    const int* __restrict__ labels,
    const float* __restrict__ centers,
    float* __restrict__ out)
{
    const int t = threadIdx.x;
    const int warp = t >> 5;          // 0..7
    const int lane = t & 31;
    const int cta = blockIdx.x;
    const int lrow = warp >> 1;       // 0..3 local row
    const int half = warp & 1;        // half of the row

    __shared__ alignas(128) float s_x[ROWS_PER_CTA * FEAT_DIM];   // 8 KB
    __shared__ alignas(128) float s_c[ROWS_PER_CTA * FEAT_DIM];   // 8 KB
    __shared__ alignas(8) unsigned long long s_mbar;
    __shared__ float s_half[8];
    __shared__ bool s_is_last;

    const uint32_t mbar = smem_u32(&s_mbar);

    if (t == 0) {
        asm volatile("mbarrier.init.shared.b64 [%0], 1;" :: "r"(mbar) : "memory");
    }
    __syncthreads();

    if (t == 0) {
        // Order the generic-proxy mbarrier init before async-proxy use.
        asm volatile("fence.proxy.async.shared::cta;" ::: "memory");

        // Labels for the CTA's 4 consecutive rows: one 16B load.
        int4 lab = *reinterpret_cast<const int4*>(labels + cta * ROWS_PER_CTA);
        int c0 = min(max(lab.x, 0), NUM_CLASSES - 1);
        int c1 = min(max(lab.y, 0), NUM_CLASSES - 1);
        int c2 = min(max(lab.z, 0), NUM_CLASSES - 1);
        int c3 = min(max(lab.w, 0), NUM_CLASSES - 1);

        asm volatile("mbarrier.arrive.expect_tx.shared.b64 _, [%0], %1;"
                     :: "r"(mbar), "r"((uint32_t)TX_BYTES) : "memory");

        // 1 bulk copy: 4 contiguous x rows (8192 B).
        const float* gx = x + (size_t)cta * ROWS_PER_CTA * FEAT_DIM;
        asm volatile(
            "cp.async.bulk.shared::cta.global.mbarrier::complete_tx::bytes "
            "[%0], [%1], %2, [%3];"
            :: "r"(smem_u32(s_x)), "l"(gx),
               "r"((uint32_t)(ROWS_PER_CTA * FEAT_DIM * 4)), "r"(mbar)
            : "memory");

        // 4 bulk copies: gathered center rows (2048 B each).
        const int cs[4] = {c0, c1, c2, c3};
        #pragma unroll
        for (int r = 0; r < 4; r++) {
            const float* gc = centers + (size_t)cs[r] * FEAT_DIM;
            asm volatile(
                "cp.async.bulk.shared::cta.global.mbarrier::complete_tx::bytes "
                "[%0], [%1], %2, [%3];"
                :: "r"(smem_u32(s_c + r * FEAT_DIM)), "l"(gc),
                   "r"((uint32_t)(FEAT_DIM * 4)), "r"(mbar)
                : "memory");
        }
    }

    // All threads wait for the 16KB of bulk data (phase 0).
    {
        uint32_t done = 0;
        while (!done) {
            asm volatile(
                "{\n\t.reg .pred p;\n\t"
                "mbarrier.try_wait.parity.acquire.cta.shared::cta.b64 p, [%1], 0, 0x989680;\n\t"
                "selp.b32 %0, 1, 0, p;\n\t}"
                : "=r"(done) : "r"(mbar) : "memory");
        }
    }

    // Compute from smem: warp covers a half-row, 8 float2 per lane.
    const float2* sxr = reinterpret_cast<const float2*>(s_x)
                        + lrow * (FEAT_DIM / 2) + half * 128;
    const float2* scr = reinterpret_cast<const float2*>(s_c)
                        + lrow * (FEAT_DIM / 2) + half * 128;

    float s = 0.0f;
    #pragma unroll
    for (int i = 0; i < 4; i++) {
        float2 a = sxr[i * 32 + lane];
        float2 b = scr[i * 32 + lane];
        float d0 = a.x - b.x, d1 = a.y - b.y;
        s += d0 * d0 + d1 * d1;
    }

    #pragma unroll
    for (int o = 16; o > 0; o >>= 1)
        s += __shfl_xor_sync(0xffffffffu, s, o);

    if (lane == 0) s_half[warp] = s;
    __syncthreads();

    if (t == 0) {
        float acc = 0.0f;
        #pragma unroll
        for (int r = 0; r < ROWS_PER_CTA; r++) {
            float rs = s_half[2 * r] + s_half[2 * r + 1];
            rs = fminf(fmaxf(rs, 1e-12f), 1e12f);   // per-row clamp
            acc += rs;
        }
        g_cta_partials[cta] = acc;
        __threadfence();
        unsigned int v = atomicAdd(&g_done_count, 1u);
        s_is_last = (v == (unsigned int)(NUM_CTAS - 1));
    }
    __syncthreads();

    if (s_is_last) {
        // 1024 partials as 256 float4: one vector load per thread.
        float4 p = reinterpret_cast<const float4*>(g_cta_partials)[t];
        float v = (p.x + p.y) + (p.z + p.w);

        #pragma unroll
        for (int o = 16; o > 0; o >>= 1)
            v += __shfl_xor_sync(0xffffffffu, v, o);

        __shared__ float fs[8];
        if (lane == 0) fs[warp] = v;
        __syncthreads();

        if (t == 0) {
            const float zero_clamp_sum =
                (float)((double)N_ROWS * (double)(NUM_CLASSES - 1) * 1e-12);
            float r = 0.0f;
            #pragma unroll
            for (int w = 0; w < 8; w++) r += fs[w];
            out[0] = r + zero_clamp_sum;
            g_done_count = 0;   // reset for next graph replay
        }
    }
}

extern "C" void kernel_launch(void* const* d_in, const int* in_sizes, int n_in,
                              void* d_out, int out_size)
{
    const float* x       = (const float*)d_in[0];  // (16,256,512) f32
    const int*   labels  = (const int*)d_in[1];    // (16,256) int32
    const float* centers = (const float*)d_in[2];  // (10000,512) f32
    float*       out     = (float*)d_out;          // scalar

    (void)in_sizes; (void)n_in; (void)out_size;

    center_loss_kernel<<<NUM_CTAS, 256>>>(x, labels, centers, out);
}

// round 17
// speedup vs baseline: 1.0859x; 1.0859x over previous
#include <cuda_runtime.h>

// CenterLoss collapses algebraically: after masking, only the true-label
// column survives; the other C-1 zeros clamp to 1e-12 each.
//   loss = sum_n clamp(||x_n - c_{lab_n}||^2, 1e-12, 1e12) + N*(C-1)*1e-12
// So the reference's 4096x10000x512 GEMM is dead work; the real computation
// is a gathered per-row squared distance + global sum.
//
// FINAL. Eleven structural variants (R4-R16) spanning occupancy 12-83%,
// MLP 2-8, LDG.64/128/256, L2 evict hints, atomic counts 256-1024, fenced
// and fence-free tails, and cp.async.bulk (TMA engine) staging ALL delivered
// 1.80-1.89 TB/s. Traffic is compulsory-minimal (15.3 MB: x once + each
// distinct center row once; L2 serves duplicates). dur = bytes / delivered
// BW ~= 8.1us at the parked-DVFS bandwidth of an isolated ~8us kernel.
// Both terms are environment-fixed -> this config (best measured: 8.128us
// kernel) is the floor.
//  - 1024 CTAs x 256 threads, half-row per warp
//  - per-warp label fetch overlapped with x loads (no pre-barrier)
//  - float2 (LDG.64) data loads, 8 per lane
//  - fused last-CTA fixed-order tail -> bitwise deterministic

#define N_ROWS 4096      // 16 * 256
#define FEAT_DIM 512
#define F2_PER_ROW (FEAT_DIM / 2)   // 256
#define NUM_CLASSES 10000
#define NUM_CTAS 1024
#define ROWS_PER_CTA 4

__device__ float g_cta_partials[NUM_CTAS];
__device__ unsigned int g_done_count = 0;

__global__ __launch_bounds__(256, 8) void center_loss_kernel(
    const float* __restrict__ x,
    const int* __restrict__ labels,
    const float* __restrict__ centers,
    float* __restrict__ out)
{
    const int t = threadIdx.x;
    const int warp = t >> 5;          // 0..7
    const int lane = t & 31;
    const int cta = blockIdx.x;
    const int lrow = warp >> 1;       // 0..3 local row
    const int half = warp & 1;        // half of the row

    const int row = cta * ROWS_PER_CTA + lrow;

    __shared__ float s_half[8];
    __shared__ bool s_is_last;

    // Label first (head of the dependent chain), per-warp, no barrier.
    int c = 0;
    if (lane == 0) c = labels[row];

    // x loads (LDG.64): independent, overlap the label latency.
    const float2* __restrict__ xr =
        reinterpret_cast<const float2*>(x) + (size_t)row * F2_PER_ROW + half * 128;
    float2 a0 = xr[lane];
    float2 a1 = xr[32 + lane];
    float2 a2 = xr[64 + lane];
    float2 a3 = xr[96 + lane];

    // Broadcast label, then the dependent center gather.
    c = __shfl_sync(0xffffffffu, c, 0);
    c = min(max(c, 0), NUM_CLASSES - 1);

    const float2* __restrict__ cr =
        reinterpret_cast<const float2*>(centers) + (size_t)c * F2_PER_ROW + half * 128;
    float2 b0 = cr[lane];
    float2 b1 = cr[32 + lane];
    float2 b2 = cr[64 + lane];
    float2 b3 = cr[96 + lane];

    float d0, d1;
    d0 = a0.x - b0.x; d1 = a0.y - b0.y;
    float s = d0 * d0 + d1 * d1;
    d0 = a1.x - b1.x; d1 = a1.y - b1.y;
    s += d0 * d0 + d1 * d1;
    d0 = a2.x - b2.x; d1 = a2.y - b2.y;
    s += d0 * d0 + d1 * d1;
    d0 = a3.x - b3.x; d1 = a3.y - b3.y;
    s += d0 * d0 + d1 * d1;

    // warp reduce -> lane 0 holds half-row sum
    #pragma unroll
    for (int o = 16; o > 0; o >>= 1)
        s += __shfl_xor_sync(0xffffffffu, s, o);

    if (lane == 0) s_half[warp] = s;
    __syncthreads();

    if (t == 0) {
        float acc = 0.0f;
        #pragma unroll
        for (int r = 0; r < ROWS_PER_CTA; r++) {
            float rs = s_half[2 * r] + s_half[2 * r + 1];
            rs = fminf(fmaxf(rs, 1e-12f), 1e12f);   // per-row clamp
            acc += rs;
        }
        g_cta_partials[cta] = acc;
        __threadfence();
        unsigned int v = atomicAdd(&g_done_count, 1u);
        s_is_last = (v == (unsigned int)(NUM_CTAS - 1));
    }
    __syncthreads();

    if (s_is_last) {
        // 1024 partials as 256 float4: one vector load per thread.
        float4 p = reinterpret_cast<const float4*>(g_cta_partials)[t];
        float v = (p.x + p.y) + (p.z + p.w);

        #pragma unroll
        for (int o = 16; o > 0; o >>= 1)
            v += __shfl_xor_sync(0xffffffffu, v, o);

        __shared__ float fs[8];
        if (lane == 0) fs[warp] = v;
        __syncthreads();

        if (t == 0) {
            const float zero_clamp_sum =
                (float)((double)N_ROWS * (double)(NUM_CLASSES - 1) * 1e-12);
            float r = 0.0f;
            #pragma unroll
            for (int w = 0; w < 8; w++) r += fs[w];
            out[0] = r + zero_clamp_sum;
            g_done_count = 0;   // reset for next graph replay
        }
    }
}

extern "C" void kernel_launch(void* const* d_in, const int* in_sizes, int n_in,
                              void* d_out, int out_size)
{
    const float* x       = (const float*)d_in[0];  // (16,256,512) f32
    const int*   labels  = (const int*)d_in[1];    // (16,256) int32
    const float* centers = (const float*)d_in[2];  // (10000,512) f32
    float*       out     = (float*)d_out;          // scalar

    (void)in_sizes; (void)n_in; (void)out_size;

    center_loss_kernel<<<NUM_CTAS, 256>>>(x, labels, centers, out);
}